// round 15
// baseline (speedup 1.0000x reference)
#include <cuda_runtime.h>
#include <cstdint>

#define N 8192
#define RANK 4
#define SCALING 2.0f   // ALPHA / RANK = 8 / 4
#define EPS 1e-5f
#define TPB 512
#define STAGES 3
#define ROW_BYTES (N * 4)                 // 32 KB per row
#define SMEM_STAGE0 128                   // stages start after barriers
#define SMEM_BYTES (SMEM_STAGE0 + STAGES * ROW_BYTES)   // 98432 B

// Allocation-free scratch for the adapted affine vectors.
__device__ float g_scale[N];
__device__ float g_shift[N];

// ---------------------------------------------------------------------------
// Kernel 1: rank-4 low-rank diagonal -> per-feature scale/shift vectors.
// ---------------------------------------------------------------------------
__global__ void lora_vectors_kernel(const float* __restrict__ sA,
                                    const float* __restrict__ sB,
                                    const float* __restrict__ hA,
                                    const float* __restrict__ hB) {
    int i = blockIdx.x * blockDim.x + threadIdx.x;
    if (i >= N) return;
    float4 a_s = *(const float4*)(sA + i * RANK);
    float4 a_h = *(const float4*)(hA + i * RANK);
    float s = a_s.x * sB[0 * N + i] + a_s.y * sB[1 * N + i]
            + a_s.z * sB[2 * N + i] + a_s.w * sB[3 * N + i];
    float h = a_h.x * hB[0 * N + i] + a_h.y * hB[1 * N + i]
            + a_h.z * hB[2 * N + i] + a_h.w * hB[3 * N + i];
    g_scale[i] = s * SCALING;
    g_shift[i] = h * SCALING;
}

// ---- mbarrier / bulk-copy helpers ----------------------------------------
__device__ __forceinline__ uint32_t smem_u32(const void* p) {
    uint32_t a;
    asm("{ .reg .u64 t; cvta.to.shared.u64 t, %1; cvt.u32.u64 %0, t; }"
        : "=r"(a) : "l"(p));
    return a;
}

#define MBAR_INIT(bar, cnt) \
    asm volatile("mbarrier.init.shared.b64 [%0], %1;" :: "r"(bar), "r"(cnt) : "memory")

#define MBAR_EXPECT_TX(bar, bytes) \
    asm volatile("mbarrier.arrive.expect_tx.shared.b64 _, [%0], %1;" \
                 :: "r"(bar), "r"(bytes) : "memory")

#define BULK_LOAD(dst_smem, gsrc, bytes, bar) \
    asm volatile("cp.async.bulk.shared::cluster.global.mbarrier::complete_tx::bytes " \
                 "[%0], [%1], %2, [%3];" \
                 :: "r"(dst_smem), "l"(gsrc), "r"(bytes), "r"(bar) : "memory")

#define MBAR_WAIT_PARITY(mbar, ph) do {                                        \
    uint32_t _m = (mbar), _p = (ph), _done;                                    \
    asm volatile("{\n\t.reg .pred p;\n\t"                                      \
        "mbarrier.try_wait.parity.acquire.cta.shared::cta.b64 p, [%1], %2;\n\t"\
        "selp.b32 %0, 1, 0, p;\n\t}"                                           \
        : "=r"(_done) : "r"(_m), "r"(_p) : "memory");                          \
    if (!_done) {                                                              \
        asm volatile("{\n\t.reg .pred P1;\n\t"                                 \
            "WAIT_LOOP_%=:\n\t"                                                \
            "mbarrier.try_wait.parity.acquire.cta.shared::cta.b64 P1, [%0], %1, 0x989680;\n\t" \
            "@P1 bra.uni WAIT_DONE_%=;\n\t"                                    \
            "bra.uni WAIT_LOOP_%=;\n\t"                                        \
            "WAIT_DONE_%=:\n\t}"                                               \
            :: "r"(_m), "r"(_p) : "memory");                                   \
    }                                                                          \
} while (0)

// ---------------------------------------------------------------------------
// Kernel 2: persistent LN with a depth-3 TMA (cp.async.bulk) input pipeline.
// CTA c handles rows c, c+G, c+2G, ... Stage s holds row for iter%3==s; it is
// refilled for iter+3 right after the reduction barrier (all LDS reads done,
// row data lives in registers from there on). Epilogue is the proven R11 form.
// ---------------------------------------------------------------------------
__global__ __launch_bounds__(TPB, 2)
void lora_ln_tma(const float* __restrict__ x, float* __restrict__ out, int rows) {
    extern __shared__ char smem[];
    const int t = threadIdx.x;
    const int lane = t & 31, warp = t >> 5;
    const int G = gridDim.x;
    const int c = blockIdx.x;
    const uint32_t sbase = smem_u32(smem);

    __shared__ float2 s_part[16];

    if (t == 0) {
#pragma unroll
        for (int s = 0; s < STAGES; s++) MBAR_INIT(sbase + s * 8, 1);
    }
    __syncthreads();

    // Prologue: fill all 3 stages.
    if (t == 0) {
#pragma unroll
        for (int p = 0; p < STAGES; p++) {
            const int row = c + p * G;
            if (row < rows) {
                const uint32_t bar = sbase + p * 8;
                const uint32_t dst = sbase + SMEM_STAGE0 + p * ROW_BYTES;
                MBAR_EXPECT_TX(bar, ROW_BYTES);
                BULK_LOAD(dst, x + (size_t)row * N, ROW_BYTES, bar);
            }
        }
    }

    const float4* __restrict__ sc = (const float4*)g_scale;
    const float4* __restrict__ sh = (const float4*)g_shift;

    int iter = 0;
    for (int row = c; row < rows; row += G, iter++) {
        const int s = iter % STAGES;
        const uint32_t bar = sbase + s * 8;
        const int parity = (iter / STAGES) & 1;

        MBAR_WAIT_PARITY(bar, parity);

        // Pull the row from smem into registers (conflict-free LDS.128).
        const float4* __restrict__ sp =
            (const float4*)(smem + SMEM_STAGE0 + s * ROW_BYTES);
        float4 v[4];
#pragma unroll
        for (int i = 0; i < 4; i++) v[i] = sp[t + i * TPB];

        float sum = 0.f, sq = 0.f;
#pragma unroll
        for (int i = 0; i < 4; i++) {
            sum += v[i].x + v[i].y + v[i].z + v[i].w;
            sq  += v[i].x * v[i].x + v[i].y * v[i].y
                 + v[i].z * v[i].z + v[i].w * v[i].w;
        }
#pragma unroll
        for (int off = 16; off > 0; off >>= 1) {
            sum += __shfl_xor_sync(0xFFFFFFFFu, sum, off);
            sq  += __shfl_xor_sync(0xFFFFFFFFu, sq,  off);
        }
        if (lane == 0) s_part[warp] = make_float2(sum, sq);
        __syncthreads();   // partials published AND all LDS reads of stage s done

        // Refill stage s with row+3G — overlaps epilogue + next two rows.
        if (t == 0) {
            const int nrow = row + STAGES * G;
            if (nrow < rows) {
                MBAR_EXPECT_TX(bar, ROW_BYTES);
                BULK_LOAD(sbase + SMEM_STAGE0 + s * ROW_BYTES,
                          x + (size_t)nrow * N, ROW_BYTES, bar);
            }
        }

        float2 p = s_part[lane & 15];
#pragma unroll
        for (int off = 8; off > 0; off >>= 1) {
            p.x += __shfl_xor_sync(0xFFFFFFFFu, p.x, off);
            p.y += __shfl_xor_sync(0xFFFFFFFFu, p.y, off);
        }
        const float mean = p.x * (1.0f / N);
        const float rstd = rsqrtf(p.y * (1.0f / N) - mean * mean + EPS);

        float4* __restrict__ yr = (float4*)(out + (size_t)row * N);
#pragma unroll
        for (int i = 0; i < 4; i++) {
            const int idx = t + i * TPB;
            float4 sv = sc[idx];
            float4 hv = sh[idx];
            float4 a, b, o;
            a.x = rstd * sv.x; a.y = rstd * sv.y; a.z = rstd * sv.z; a.w = rstd * sv.w;
            b.x = hv.x - mean * a.x; b.y = hv.y - mean * a.y;
            b.z = hv.z - mean * a.z; b.w = hv.w - mean * a.w;
            o.x = v[i].x * a.x + b.x; o.y = v[i].y * a.y + b.y;
            o.z = v[i].z * a.z + b.z; o.w = v[i].w * a.w + b.w;
            __stcs(yr + idx, o);
        }
    }
}

extern "C" void kernel_launch(void* const* d_in, const int* in_sizes, int n_in,
                              void* d_out, int out_size) {
    const float* x  = (const float*)d_in[0];
    const float* sA = (const float*)d_in[1];
    const float* sB = (const float*)d_in[2];
    const float* hA = (const float*)d_in[3];
    const float* hB = (const float*)d_in[4];
    float* out = (float*)d_out;

    const int rows = out_size / N;   // 8192

    int dev = 0, sm = 148;
    cudaGetDevice(&dev);
    cudaDeviceGetAttribute(&sm, cudaDevAttrMultiProcessorCount, dev);
    const int grid = 2 * sm;         // 2 CTAs/SM (96 KB smem each)

    cudaFuncSetAttribute(lora_ln_tma,
                         cudaFuncAttributeMaxDynamicSharedMemorySize, SMEM_BYTES);

    lora_vectors_kernel<<<128, 64>>>(sA, sB, hA, hB);
    lora_ln_tma<<<grid, TPB, SMEM_BYTES>>>(x, out, rows);
}